// round 1
// baseline (speedup 1.0000x reference)
#include <cuda_runtime.h>

#define TB 64          // tokens per CTA
#define NT 256         // threads per CTA
#define SXS 132        // sX row stride (floats), 128 + 4 pad
#define SQS 388        // sQKV row stride (floats), 384 + 4 pad

// ---- packed fp32x2 helpers (sm_103a FFMA2 path, PTX-only) ----
__device__ __forceinline__ unsigned long long pack2f(float lo, float hi) {
    unsigned long long r;
    asm("mov.b64 %0, {%1, %2};" : "=l"(r) : "f"(lo), "f"(hi));
    return r;
}
__device__ __forceinline__ unsigned long long ffma2(unsigned long long a,
                                                    unsigned long long b,
                                                    unsigned long long c) {
    unsigned long long d;
    asm("fma.rn.f32x2 %0, %1, %2, %3;" : "=l"(d) : "l"(a), "l"(b), "l"(c));
    return d;
}
__device__ __forceinline__ unsigned long long fadd2(unsigned long long a,
                                                    unsigned long long b) {
    unsigned long long d;
    asm("add.rn.f32x2 %0, %1, %2;" : "=l"(d) : "l"(a), "l"(b));
    return d;
}

// Fused: qkv = x@Wqkv + b; per-token/per-head 16x16 softmax-combine; out = a@Wproj + b
__global__ void __launch_bounds__(NT, 1)
chan_attn_kernel(const float* __restrict__ x,
                 const float* __restrict__ w_qkv,
                 const float* __restrict__ b_qkv,
                 const float* __restrict__ w_proj,
                 const float* __restrict__ b_proj,
                 float* __restrict__ out)
{
    extern __shared__ float smem[];
    float* sX   = smem;              // [TB][SXS]   33792 B
    float* sW   = smem + TB * SXS;   // [16][384]   24576 B (panel, reused in GEMM2)
    float* sQKV = sW + 16 * 384;     // [TB][SQS]   99328 B
    float* sOut = sX;                // alias: attention output reuses sX region

    const int tid = threadIdx.x;
    const long long tokenBase = (long long)blockIdx.x * TB;

    // ---------------- Phase 1: load x tile (coalesced) ----------------
    {
        const float4* x4 = (const float4*)(x + tokenBase * 128);
        #pragma unroll
        for (int i = tid; i < TB * 32; i += NT) {
            int t = i >> 5, c4 = i & 31;
            float4 v = x4[i];
            float* dst = sX + t * SXS + c4 * 4;
            dst[0] = v.x; dst[1] = v.y; dst[2] = v.z; dst[3] = v.w;
        }
    }

    const int tx = tid & 15;   // column group
    const int ty = tid >> 4;   // row group: 4 tokens

    // ---------------- Phase 2: GEMM1  qkv[64][384] ----------------
    // per-thread microtile: 4 rows x 24 cols (cols = g*64 + tx*4, g=0..5), f32x2 packed
    unsigned long long acc1[4][12];
    #pragma unroll
    for (int r = 0; r < 4; r++)
        #pragma unroll
        for (int i = 0; i < 12; i++) acc1[r][i] = 0ULL;

    #pragma unroll 1
    for (int p = 0; p < 8; p++) {
        __syncthreads();
        // stream 16x384 weight panel to smem
        const float4* wq4 = (const float4*)(w_qkv + p * 16 * 384);
        float4* sW4 = (float4*)sW;
        #pragma unroll
        for (int i = tid; i < 16 * 96; i += NT) sW4[i] = wq4[i];
        __syncthreads();

        #pragma unroll 4
        for (int kk = 0; kk < 16; kk++) {
            unsigned long long ap[4];
            #pragma unroll
            for (int r = 0; r < 4; r++) {
                float a = sX[(ty * 4 + r) * SXS + p * 16 + kk];
                ap[r] = pack2f(a, a);
            }
            #pragma unroll
            for (int g = 0; g < 6; g++) {
                ulonglong2 b = *(const ulonglong2*)(sW + kk * 384 + g * 64 + tx * 4);
                #pragma unroll
                for (int r = 0; r < 4; r++) {
                    acc1[r][g * 2]     = ffma2(ap[r], b.x, acc1[r][g * 2]);
                    acc1[r][g * 2 + 1] = ffma2(ap[r], b.y, acc1[r][g * 2 + 1]);
                }
            }
        }
    }
    // epilogue: + bias, store to sQKV
    #pragma unroll
    for (int g = 0; g < 6; g++) {
        ulonglong2 bb = *(const ulonglong2*)(b_qkv + g * 64 + tx * 4);
        #pragma unroll
        for (int r = 0; r < 4; r++) {
            ulonglong2 o;
            o.x = fadd2(acc1[r][g * 2], bb.x);
            o.y = fadd2(acc1[r][g * 2 + 1], bb.y);
            *(ulonglong2*)(sQKV + (ty * 4 + r) * SQS + g * 64 + tx * 4) = o;
        }
    }
    __syncthreads();

    // ---------------- Phase 3: per-token per-head softmax combine ----------------
    // unit = (token, head): out_i = sum_j softmax_j(scale*q_i*k_j) * v_j
    const float scale = 0.0883883476483184405f;  // 128^-0.5 (NOT head_dim^-0.5)
    #pragma unroll 1
    for (int u = tid; u < TB * 8; u += NT) {
        int t = u >> 3, h = u & 7;
        const float* row = sQKV + t * SQS + h * 16;
        float q[16], k[16], v[16];
        #pragma unroll
        for (int i = 0; i < 16; i++) q[i] = row[i];
        #pragma unroll
        for (int i = 0; i < 16; i++) k[i] = row[128 + i];
        #pragma unroll
        for (int i = 0; i < 16; i++) v[i] = row[256 + i];

        float kmax = k[0], kmin = k[0];
        #pragma unroll
        for (int i = 1; i < 16; i++) { kmax = fmaxf(kmax, k[i]); kmin = fminf(kmin, k[i]); }

        float* od = sOut + t * SXS + h * 16;
        #pragma unroll 2
        for (int i = 0; i < 16; i++) {
            float c = q[i] * scale;
            float m = (c >= 0.f) ? c * kmax : c * kmin;   // row max of logits
            float s = 0.f, a = 0.f;
            #pragma unroll
            for (int j = 0; j < 16; j++) {
                float e = __expf(fmaf(c, k[j], -m));
                s += e;
                a = fmaf(e, v[j], a);
            }
            od[i] = __fdividef(a, s);
        }
    }
    __syncthreads();

    // ---------------- Phase 4: GEMM2  out[64][128] = sOut @ Wproj + b ----------------
    unsigned long long acc2[4][4];   // 4 rows x (2 groups x 2 pairs) = 32 cols
    #pragma unroll
    for (int r = 0; r < 4; r++)
        #pragma unroll
        for (int i = 0; i < 4; i++) acc2[r][i] = 0ULL;

    #pragma unroll 1
    for (int p = 0; p < 8; p++) {
        __syncthreads();
        const float4* wp4 = (const float4*)(w_proj + p * 16 * 128);
        float4* sW4 = (float4*)sW;
        #pragma unroll
        for (int i = tid; i < 16 * 32; i += NT) sW4[i] = wp4[i];
        __syncthreads();

        #pragma unroll 4
        for (int kk = 0; kk < 16; kk++) {
            unsigned long long ap[4];
            #pragma unroll
            for (int r = 0; r < 4; r++) {
                float a = sOut[(ty * 4 + r) * SXS + p * 16 + kk];
                ap[r] = pack2f(a, a);
            }
            #pragma unroll
            for (int g = 0; g < 2; g++) {
                ulonglong2 b = *(const ulonglong2*)(sW + kk * 128 + g * 64 + tx * 4);
                #pragma unroll
                for (int r = 0; r < 4; r++) {
                    acc2[r][g * 2]     = ffma2(ap[r], b.x, acc2[r][g * 2]);
                    acc2[r][g * 2 + 1] = ffma2(ap[r], b.y, acc2[r][g * 2 + 1]);
                }
            }
        }
    }
    // epilogue: + bias, store to gmem
    #pragma unroll
    for (int g = 0; g < 2; g++) {
        ulonglong2 bb = *(const ulonglong2*)(b_proj + g * 64 + tx * 4);
        #pragma unroll
        for (int r = 0; r < 4; r++) {
            ulonglong2 o;
            o.x = fadd2(acc2[r][g * 2], bb.x);
            o.y = fadd2(acc2[r][g * 2 + 1], bb.y);
            *(ulonglong2*)(out + (tokenBase + ty * 4 + r) * 128 + g * 64 + tx * 4) = o;
        }
    }
}

extern "C" void kernel_launch(void* const* d_in, const int* in_sizes, int n_in,
                              void* d_out, int out_size)
{
    // Map inputs defensively by element count (all sizes are distinct):
    // x = tokens*128 (largest), w_qkv = 49152, b_qkv = 384, w_proj = 16384, b_proj = 128
    const float *x = nullptr, *wq = nullptr, *bq = nullptr, *wp = nullptr, *bp = nullptr;
    long long xsz = 0;
    for (int i = 0; i < n_in; i++) {
        switch (in_sizes[i]) {
            case 49152: wq = (const float*)d_in[i]; break;
            case 384:   bq = (const float*)d_in[i]; break;
            case 16384: wp = (const float*)d_in[i]; break;
            case 128:   bp = (const float*)d_in[i]; break;
            default:    x  = (const float*)d_in[i]; xsz = in_sizes[i]; break;
        }
    }
    const int tokens = (int)(xsz / 128);
    const int smem_bytes = (TB * SXS + 16 * 384 + TB * SQS) * (int)sizeof(float); // 157696

    cudaFuncSetAttribute(chan_attn_kernel,
                         cudaFuncAttributeMaxDynamicSharedMemorySize, smem_bytes);

    dim3 grid(tokens / TB);
    chan_attn_kernel<<<grid, NT, smem_bytes>>>(x, wq, bq, wp, bp, (float*)d_out);
}

// round 3
// speedup vs baseline: 1.5566x; 1.5566x over previous
#include <cuda_runtime.h>
#include <cuda_bf16.h>

#define NT 256
#define TOK 128

// Pre-swizzled [N][K] bf16 weight images (hi/lo split). Row = N (out col),
// 128 K values * 2B = 256B per row, 16B-chunk XOR swizzle within row.
__device__ __align__(16) unsigned char g_b1h[98304];   // w_qkv hi  [384][128]
__device__ __align__(16) unsigned char g_b1l[98304];   // w_qkv lo
__device__ __align__(16) unsigned char g_b2h[32768];   // w_proj hi [128][128]
__device__ __align__(16) unsigned char g_b2l[32768];   // w_proj lo

#define SWZ(r, b) ((unsigned)((r) * 256 + ((b) ^ (((r) & 7) << 4))))

// smem map (bytes): biases | A hi | A lo | B hi | B lo | qkv fp32 (64 x 388)
#define OF_BQ   0u
#define OF_BP   1536u
#define OF_AH   2048u
#define OF_AL   34816u
#define OF_BH   67584u
#define OF_BL   100352u
#define OF_QKV  133120u
#define SMEM_TOTAL 232448   // == 227 KB opt-in max
#define QS 388              // qkv row stride in floats

__device__ __forceinline__ unsigned smem_u32(const void* p) {
    unsigned a;
    asm("{ .reg .u64 t; cvta.to.shared.u64 t, %1; cvt.u32.u64 %0, t; }" : "=r"(a) : "l"(p));
    return a;
}
__device__ __forceinline__ unsigned pk2(float a, float b) {
    __nv_bfloat162 t = __floats2bfloat162_rn(a, b);
    return *reinterpret_cast<unsigned*>(&t);
}
__device__ __forceinline__ float bfr(float v) {
    return __bfloat162float(__float2bfloat16_rn(v));
}

__device__ __forceinline__ void ldsm4(unsigned* r, unsigned addr) {
    asm volatile("ldmatrix.sync.aligned.m8n8.x4.shared.b16 {%0,%1,%2,%3}, [%4];"
                 : "=r"(r[0]), "=r"(r[1]), "=r"(r[2]), "=r"(r[3]) : "r"(addr));
}
__device__ __forceinline__ void mma16816(float* d, const unsigned* a, const unsigned* b) {
    asm volatile(
        "mma.sync.aligned.m16n8k16.row.col.f32.bf16.bf16.f32 "
        "{%0,%1,%2,%3}, {%4,%5,%6,%7}, {%8,%9}, {%0,%1,%2,%3};"
        : "+f"(d[0]), "+f"(d[1]), "+f"(d[2]), "+f"(d[3])
        : "r"(a[0]), "r"(a[1]), "r"(a[2]), "r"(a[3]), "r"(b[0]), "r"(b[1]));
}

// ---------------- prep: fp32 weights -> swizzled [N][K] bf16 hi/lo images ----------------
__global__ void prep_weights(const float* __restrict__ wq, const float* __restrict__ wp) {
    int i = blockIdx.x * blockDim.x + threadIdx.x;
    if (i < 6144) {                       // w_qkv: 384 n-rows x 16 chunks of 8 k
        int n = i >> 4, kc = i & 15, k0 = kc * 8;
        float hf[8], lf[8];
        #pragma unroll
        for (int j = 0; j < 8; j++) {
            float v = wq[(k0 + j) * 384 + n];
            hf[j] = bfr(v);
            lf[j] = v - hf[j];
        }
        unsigned off = SWZ(n, kc * 16);
        *(uint4*)(g_b1h + off) = make_uint4(pk2(hf[0], hf[1]), pk2(hf[2], hf[3]),
                                            pk2(hf[4], hf[5]), pk2(hf[6], hf[7]));
        *(uint4*)(g_b1l + off) = make_uint4(pk2(lf[0], lf[1]), pk2(lf[2], lf[3]),
                                            pk2(lf[4], lf[5]), pk2(lf[6], lf[7]));
    } else if (i < 8192) {                // w_proj: 128 n-rows x 16 chunks
        int j2 = i - 6144;
        int n = j2 >> 4, kc = j2 & 15, k0 = kc * 8;
        float hf[8], lf[8];
        #pragma unroll
        for (int j = 0; j < 8; j++) {
            float v = wp[(k0 + j) * 128 + n];
            hf[j] = bfr(v);
            lf[j] = v - hf[j];
        }
        unsigned off = SWZ(n, kc * 16);
        *(uint4*)(g_b2h + off) = make_uint4(pk2(hf[0], hf[1]), pk2(hf[2], hf[3]),
                                            pk2(hf[4], hf[5]), pk2(hf[6], hf[7]));
        *(uint4*)(g_b2l + off) = make_uint4(pk2(lf[0], lf[1]), pk2(lf[2], lf[3]),
                                            pk2(lf[4], lf[5]), pk2(lf[6], lf[7]));
    }
}

// ---------------- main fused kernel ----------------
__global__ void __launch_bounds__(NT, 1)
chan_attn_mma(const float* __restrict__ x, const float* __restrict__ bq,
              const float* __restrict__ bp, float* __restrict__ out)
{
    extern __shared__ __align__(16) unsigned char smem[];
    const unsigned sb = smem_u32(smem);
    const int tid = threadIdx.x, wid = tid >> 5, lane = tid & 31;
    const long long tb = (long long)blockIdx.x * TOK;

    float* sBq = (float*)(smem + OF_BQ);
    float* sBp = (float*)(smem + OF_BP);
    float* qkv = (float*)(smem + OF_QKV);

    for (int i = tid; i < 384; i += NT) sBq[i] = bq[i];
    if (tid < 128) sBp[tid] = bp[tid];

    // build A image from x (hi/lo bf16, swizzled [m][k])
    {
        const float4* x4 = (const float4*)(x + tb * 128);
        #pragma unroll 4
        for (int i = tid; i < TOK * 32; i += NT) {
            int m = i >> 5, c4 = i & 31;
            float4 v = x4[i];
            float h0 = bfr(v.x), h1 = bfr(v.y), h2 = bfr(v.z), h3 = bfr(v.w);
            unsigned off = SWZ(m, c4 * 8);
            *(uint2*)(smem + OF_AH + off) = make_uint2(pk2(h0, h1), pk2(h2, h3));
            *(uint2*)(smem + OF_AL + off) =
                make_uint2(pk2(v.x - h0, v.y - h1), pk2(v.z - h2, v.w - h3));
        }
    }

    // ldmatrix lane address components
    const int a_r = (lane & 7) + ((lane >> 3) & 1) * 8;   // A: row offset within m16
    const int a_bs = (lane >> 4) * 16;                    // A: k-byte offset
    const int b_r = (lane & 7) + (lane >> 4) * 8;         // B: n offset within n16
    const int b_bs = ((lane >> 3) & 1) * 16;              // B: k-byte offset

    const float scl = 0.0883883476483184405f;  // 128^-0.5

    #pragma unroll 1
    for (int half = 0; half < 2; half++) {
        // ---- GEMM1: qkv[64][384] for this half, 3 N-chunks of 128 ----
        const int wm = wid >> 2, wn = wid & 3;   // 2M x 4N warp grid
        #pragma unroll 1
        for (int c = 0; c < 3; c++) {
            __syncthreads();
            {   // fill B chunk (already-swizzled images, linear copy)
                const uint4* shc = (const uint4*)(g_b1h + c * 32768);
                const uint4* slc = (const uint4*)(g_b1l + c * 32768);
                uint4* dh = (uint4*)(smem + OF_BH);
                uint4* dl = (uint4*)(smem + OF_BL);
                #pragma unroll 4
                for (int i = tid; i < 2048; i += NT) { dh[i] = shc[i]; dl[i] = slc[i]; }
            }
            __syncthreads();

            float d[2][4][4] = {};
            const int arow0 = half * 64 + wm * 32 + a_r;
            const int brow0 = wn * 32 + b_r;
            #pragma unroll
            for (int kc = 0; kc < 8; kc++) {
                const int kb = kc * 32;
                unsigned ah[2][4], al[2][4], bh[2][4], bl[2][4];
                #pragma unroll
                for (int mi = 0; mi < 2; mi++) {
                    unsigned off = SWZ(arow0 + mi * 16, kb + a_bs);
                    ldsm4(ah[mi], sb + OF_AH + off);
                    ldsm4(al[mi], sb + OF_AL + off);
                }
                #pragma unroll
                for (int nj = 0; nj < 2; nj++) {
                    unsigned off = SWZ(brow0 + nj * 16, kb + b_bs);
                    ldsm4(bh[nj], sb + OF_BH + off);
                    ldsm4(bl[nj], sb + OF_BL + off);
                }
                #pragma unroll
                for (int mi = 0; mi < 2; mi++)
                    #pragma unroll
                    for (int n8 = 0; n8 < 4; n8++) {
                        const unsigned* BH = bh[n8 >> 1] + (n8 & 1) * 2;
                        const unsigned* BL = bl[n8 >> 1] + (n8 & 1) * 2;
                        mma16816(d[mi][n8], ah[mi], BH);
                        mma16816(d[mi][n8], ah[mi], BL);
                        mma16816(d[mi][n8], al[mi], BH);
                    }
            }
            // flush D -> qkv (token-local rows, fp32)
            const int rloc = wm * 32 + (lane >> 2);
            const int cbas = c * 128 + wn * 32 + (lane & 3) * 2;
            #pragma unroll
            for (int mi = 0; mi < 2; mi++)
                #pragma unroll
                for (int n8 = 0; n8 < 4; n8++) {
                    int row = rloc + mi * 16, col = cbas + n8 * 8;
                    *(float2*)(qkv + row * QS + col) =
                        make_float2(d[mi][n8][0], d[mi][n8][1]);
                    *(float2*)(qkv + (row + 8) * QS + col) =
                        make_float2(d[mi][n8][2], d[mi][n8][3]);
                }
        }
        __syncthreads();

        // ---- softmax for this half; writes A2 image over dead A rows ----
        const int h = lane >> 2;
        #pragma unroll 1
        for (int u = 0; u < 2; u++) {
            const int t = wid * 8 + (lane & 3) + u * 4;     // token local to half
            const float* row = qkv + t * QS;
            float q[16], k[16], v[16];
            #pragma unroll
            for (int j4 = 0; j4 < 4; j4++) {
                float4 a = *(const float4*)(row + h * 16 + j4 * 4);
                float4 b = *(const float4*)(row + 128 + h * 16 + j4 * 4);
                float4 cc = *(const float4*)(row + 256 + h * 16 + j4 * 4);
                const float* g0 = sBq + h * 16 + j4 * 4;
                q[j4 * 4 + 0] = a.x + g0[0];   q[j4 * 4 + 1] = a.y + g0[1];
                q[j4 * 4 + 2] = a.z + g0[2];   q[j4 * 4 + 3] = a.w + g0[3];
                const float* g1 = g0 + 128;
                k[j4 * 4 + 0] = b.x + g1[0];   k[j4 * 4 + 1] = b.y + g1[1];
                k[j4 * 4 + 2] = b.z + g1[2];   k[j4 * 4 + 3] = b.w + g1[3];
                const float* g2 = g0 + 256;
                v[j4 * 4 + 0] = cc.x + g2[0];  v[j4 * 4 + 1] = cc.y + g2[1];
                v[j4 * 4 + 2] = cc.z + g2[2];  v[j4 * 4 + 3] = cc.w + g2[3];
            }
            float kmax = k[0], kmin = k[0];
            #pragma unroll
            for (int i = 1; i < 16; i++) { kmax = fmaxf(kmax, k[i]); kmin = fminf(kmin, k[i]); }
            float o[16];
            #pragma unroll 2
            for (int i = 0; i < 16; i++) {
                float ci = q[i] * scl;
                float mx = (ci >= 0.f) ? ci * kmax : ci * kmin;
                float s = 0.f, acc = 0.f;
                #pragma unroll
                for (int j = 0; j < 16; j++) {
                    float e = __expf(fmaf(ci, k[j], -mx));
                    s += e;
                    acc = fmaf(e, v[j], acc);
                }
                o[i] = __fdividef(acc, s);
            }
            // write hi/lo bf16 into A image, row m = global token within CTA
            const int m = half * 64 + t;
            unsigned hi[8], lo[8];
            #pragma unroll
            for (int i = 0; i < 8; i++) {
                float h0 = bfr(o[2 * i]), h1 = bfr(o[2 * i + 1]);
                hi[i] = pk2(h0, h1);
                lo[i] = pk2(o[2 * i] - h0, o[2 * i + 1] - h1);
            }
            unsigned o0 = SWZ(m, h * 32), o1 = SWZ(m, h * 32 + 16);
            *(uint4*)(smem + OF_AH + o0) = make_uint4(hi[0], hi[1], hi[2], hi[3]);
            *(uint4*)(smem + OF_AH + o1) = make_uint4(hi[4], hi[5], hi[6], hi[7]);
            *(uint4*)(smem + OF_AL + o0) = make_uint4(lo[0], lo[1], lo[2], lo[3]);
            *(uint4*)(smem + OF_AL + o1) = make_uint4(lo[4], lo[5], lo[6], lo[7]);
        }
    }

    // ---- GEMM2: out[128][128] = A2 @ Wproj + bias ----
    __syncthreads();
    {   // fill B with proj images
        const uint4* shc = (const uint4*)(g_b2h);
        const uint4* slc = (const uint4*)(g_b2l);
        uint4* dh = (uint4*)(smem + OF_BH);
        uint4* dl = (uint4*)(smem + OF_BL);
        #pragma unroll 4
        for (int i = tid; i < 2048; i += NT) { dh[i] = shc[i]; dl[i] = slc[i]; }
    }
    __syncthreads();

    const int wm2 = wid >> 1, wn2 = wid & 1;   // 4M x 2N warp grid
    float d2[2][8][4] = {};
    const int arow0 = wm2 * 32 + a_r;
    const int brow0 = wn2 * 64 + b_r;
    #pragma unroll
    for (int kc = 0; kc < 8; kc++) {
        const int kb = kc * 32;
        unsigned ah[2][4], al[2][4], bh[4][4], bl[4][4];
        #pragma unroll
        for (int mi = 0; mi < 2; mi++) {
            unsigned off = SWZ(arow0 + mi * 16, kb + a_bs);
            ldsm4(ah[mi], sb + OF_AH + off);
            ldsm4(al[mi], sb + OF_AL + off);
        }
        #pragma unroll
        for (int nj = 0; nj < 4; nj++) {
            unsigned off = SWZ(brow0 + nj * 16, kb + b_bs);
            ldsm4(bh[nj], sb + OF_BH + off);
            ldsm4(bl[nj], sb + OF_BL + off);
        }
        #pragma unroll
        for (int mi = 0; mi < 2; mi++)
            #pragma unroll
            for (int n8 = 0; n8 < 8; n8++) {
                const unsigned* BH = bh[n8 >> 1] + (n8 & 1) * 2;
                const unsigned* BL = bl[n8 >> 1] + (n8 & 1) * 2;
                mma16816(d2[mi][n8], ah[mi], BH);
                mma16816(d2[mi][n8], ah[mi], BL);
                mma16816(d2[mi][n8], al[mi], BH);
            }
    }
    // epilogue: +bias, direct global stores (32B sectors)
    {
        float* og = out + tb * 128;
        const int rl = wm2 * 32 + (lane >> 2);
        const int cb = wn2 * 64 + (lane & 3) * 2;
        #pragma unroll
        for (int n8 = 0; n8 < 8; n8++) {
            int col = cb + n8 * 8;
            float b0 = sBp[col], b1 = sBp[col + 1];
            #pragma unroll
            for (int mi = 0; mi < 2; mi++) {
                int r0 = rl + mi * 16;
                *(float2*)(og + r0 * 128 + col) =
                    make_float2(d2[mi][n8][0] + b0, d2[mi][n8][1] + b1);
                *(float2*)(og + (r0 + 8) * 128 + col) =
                    make_float2(d2[mi][n8][2] + b0, d2[mi][n8][3] + b1);
            }
        }
    }
}

extern "C" void kernel_launch(void* const* d_in, const int* in_sizes, int n_in,
                              void* d_out, int out_size)
{
    const float *x = nullptr, *wq = nullptr, *bq = nullptr, *wp = nullptr, *bp = nullptr;
    long long xsz = 0;
    for (int i = 0; i < n_in; i++) {
        switch (in_sizes[i]) {
            case 49152: wq = (const float*)d_in[i]; break;
            case 384:   bq = (const float*)d_in[i]; break;
            case 16384: wp = (const float*)d_in[i]; break;
            case 128:   bp = (const float*)d_in[i]; break;
            default:    x  = (const float*)d_in[i]; xsz = in_sizes[i]; break;
        }
    }
    const int tokens = (int)(xsz / 128);

    prep_weights<<<32, 256>>>(wq, wp);

    cudaFuncSetAttribute(chan_attn_mma,
                         cudaFuncAttributeMaxDynamicSharedMemorySize, SMEM_TOTAL);
    chan_attn_mma<<<tokens / TOK, NT, SMEM_TOTAL>>>(x, bq, bp, (float*)d_out);
}

// round 4
// speedup vs baseline: 1.8125x; 1.1644x over previous
#include <cuda_runtime.h>
#include <cuda_bf16.h>

#define NT 512
#define TOK 128

// Pre-swizzled [N][K] bf16 weight images (hi/lo split). Row = N (out col),
// 128 K values * 2B = 256B per row, 16B-chunk XOR swizzle within row.
__device__ __align__(16) unsigned char g_b1h[98304];   // w_qkv hi  [384][128]
__device__ __align__(16) unsigned char g_b1l[98304];   // w_qkv lo
__device__ __align__(16) unsigned char g_b2h[32768];   // w_proj hi [128][128]
__device__ __align__(16) unsigned char g_b2l[32768];   // w_proj lo

#define SWZ(r, b) ((unsigned)((r) * 256 + ((b) ^ (((r) & 7) << 4))))

// smem map (bytes): biases | A hi | A lo | B hi | B lo | qkv fp32 (64 x 388)
#define OF_BQ   0u
#define OF_BP   1536u
#define OF_AH   2048u
#define OF_AL   34816u
#define OF_BH   67584u
#define OF_BL   100352u
#define OF_QKV  133120u
#define SMEM_TOTAL 232448   // max opt-in
#define QS 388              // qkv row stride in floats

__device__ __forceinline__ unsigned smem_u32(const void* p) {
    unsigned a;
    asm("{ .reg .u64 t; cvta.to.shared.u64 t, %1; cvt.u32.u64 %0, t; }" : "=r"(a) : "l"(p));
    return a;
}
__device__ __forceinline__ unsigned pk2(float a, float b) {
    __nv_bfloat162 t = __floats2bfloat162_rn(a, b);
    return *reinterpret_cast<unsigned*>(&t);
}
__device__ __forceinline__ float bfr(float v) {
    return __bfloat162float(__float2bfloat16_rn(v));
}
__device__ __forceinline__ void ldsm4(unsigned* r, unsigned addr) {
    asm volatile("ldmatrix.sync.aligned.m8n8.x4.shared.b16 {%0,%1,%2,%3}, [%4];"
                 : "=r"(r[0]), "=r"(r[1]), "=r"(r[2]), "=r"(r[3]) : "r"(addr));
}
__device__ __forceinline__ void mma16816(float* d, const unsigned* a, const unsigned* b) {
    asm volatile(
        "mma.sync.aligned.m16n8k16.row.col.f32.bf16.bf16.f32 "
        "{%0,%1,%2,%3}, {%4,%5,%6,%7}, {%8,%9}, {%0,%1,%2,%3};"
        : "+f"(d[0]), "+f"(d[1]), "+f"(d[2]), "+f"(d[3])
        : "r"(a[0]), "r"(a[1]), "r"(a[2]), "r"(a[3]), "r"(b[0]), "r"(b[1]));
}
__device__ __forceinline__ void cp16(unsigned dst, const void* src) {
    asm volatile("cp.async.cg.shared.global [%0], [%1], 16;" :: "r"(dst), "l"(src));
}
__device__ __forceinline__ float ex2f(float x) {
    float r;
    asm("ex2.approx.f32 %0, %1;" : "=f"(r) : "f"(x));
    return r;
}
__device__ __forceinline__ float rcpf(float x) {
    float r;
    asm("rcp.approx.f32 %0, %1;" : "=f"(r) : "f"(x));
    return r;
}

// ---------------- prep: fp32 weights -> swizzled [N][K] bf16 hi/lo images ----------------
__global__ void prep_weights(const float* __restrict__ wq, const float* __restrict__ wp) {
    int i = blockIdx.x * blockDim.x + threadIdx.x;
    if (i < 6144) {                       // w_qkv: 384 n-rows x 16 chunks of 8 k
        int n = i >> 4, kc = i & 15, k0 = kc * 8;
        float hf[8], lf[8];
        #pragma unroll
        for (int j = 0; j < 8; j++) {
            float v = wq[(k0 + j) * 384 + n];
            hf[j] = bfr(v);
            lf[j] = v - hf[j];
        }
        unsigned off = SWZ(n, kc * 16);
        *(uint4*)(g_b1h + off) = make_uint4(pk2(hf[0], hf[1]), pk2(hf[2], hf[3]),
                                            pk2(hf[4], hf[5]), pk2(hf[6], hf[7]));
        *(uint4*)(g_b1l + off) = make_uint4(pk2(lf[0], lf[1]), pk2(lf[2], lf[3]),
                                            pk2(lf[4], lf[5]), pk2(lf[6], lf[7]));
    } else if (i < 8192) {                // w_proj: 128 n-rows x 16 chunks
        int j2 = i - 6144;
        int n = j2 >> 4, kc = j2 & 15, k0 = kc * 8;
        float hf[8], lf[8];
        #pragma unroll
        for (int j = 0; j < 8; j++) {
            float v = wp[(k0 + j) * 128 + n];
            hf[j] = bfr(v);
            lf[j] = v - hf[j];
        }
        unsigned off = SWZ(n, kc * 16);
        *(uint4*)(g_b2h + off) = make_uint4(pk2(hf[0], hf[1]), pk2(hf[2], hf[3]),
                                            pk2(hf[4], hf[5]), pk2(hf[6], hf[7]));
        *(uint4*)(g_b2l + off) = make_uint4(pk2(lf[0], lf[1]), pk2(lf[2], lf[3]),
                                            pk2(lf[4], lf[5]), pk2(lf[6], lf[7]));
    }
}

// ---------------- main fused kernel (512 threads) ----------------
__global__ void __launch_bounds__(NT, 1)
chan_attn_mma(const float* __restrict__ x, const float* __restrict__ bq,
              const float* __restrict__ bp, float* __restrict__ out)
{
    extern __shared__ __align__(16) unsigned char smem[];
    const unsigned sb = smem_u32(smem);
    const int tid = threadIdx.x, wid = tid >> 5, lane = tid & 31;
    const long long tb = (long long)blockIdx.x * TOK;

    float* sBq = (float*)(smem + OF_BQ);
    float* sBp = (float*)(smem + OF_BP);
    float* qkv = (float*)(smem + OF_QKV);

    if (tid < 384) sBq[tid] = bq[tid];
    if (tid < 128) sBp[tid] = bp[tid];

    // prefetch B chunk (h0,c0) via cp.async
    {
        #pragma unroll
        for (int it = 0; it < 4; it++) {
            int i = tid + it * NT;
            cp16(sb + OF_BH + i * 16, g_b1h + i * 16);
            cp16(sb + OF_BL + i * 16, g_b1l + i * 16);
        }
        asm volatile("cp.async.commit_group;" ::: "memory");
    }

    // build A image from x (hi/lo bf16, swizzled [m][k]) — overlaps cp.async
    {
        const float4* x4 = (const float4*)(x + tb * 128);
        #pragma unroll
        for (int it = 0; it < 8; it++) {
            int i = tid + it * NT;
            int m = i >> 5, c4 = i & 31;
            float4 v = x4[i];
            float h0 = bfr(v.x), h1 = bfr(v.y), h2 = bfr(v.z), h3 = bfr(v.w);
            unsigned off = SWZ(m, c4 * 8);
            *(uint2*)(smem + OF_AH + off) = make_uint2(pk2(h0, h1), pk2(h2, h3));
            *(uint2*)(smem + OF_AL + off) =
                make_uint2(pk2(v.x - h0, v.y - h1), pk2(v.z - h2, v.w - h3));
        }
    }
    asm volatile("cp.async.wait_group 0;" ::: "memory");
    __syncthreads();

    // ldmatrix lane address components
    const int a_r = (lane & 7) + ((lane >> 3) & 1) * 8;
    const int a_bs = (lane >> 4) * 16;
    const int b_r = (lane & 7) + (lane >> 4) * 8;
    const int b_bs = ((lane >> 3) & 1) * 16;

    const int w8 = wid & 7;          // tile id for GEMM1 (K-split pairs)
    const int ksel = wid >> 3;       // 0: kc 0-3, 1: kc 4-7
    const int wm = w8 >> 2, wn = w8 & 3;     // 2M x 4N over (64 x 128)

    #pragma unroll 1
    for (int half = 0; half < 2; half++) {
        #pragma unroll 1
        for (int c = 0; c < 3; c++) {
            // B for (half, c) is resident & visible here
            float d[2][4][4] = {};
            const int arow0 = half * 64 + wm * 32 + a_r;
            const int brow0 = wn * 32 + b_r;
            #pragma unroll
            for (int j = 0; j < 4; j++) {
                const int kb = (ksel * 4 + j) * 32;
                unsigned ah[2][4], al[2][4], bh[2][4], bl[2][4];
                #pragma unroll
                for (int mi = 0; mi < 2; mi++) {
                    unsigned off = SWZ(arow0 + mi * 16, kb + a_bs);
                    ldsm4(ah[mi], sb + OF_AH + off);
                    ldsm4(al[mi], sb + OF_AL + off);
                }
                #pragma unroll
                for (int nj = 0; nj < 2; nj++) {
                    unsigned off = SWZ(brow0 + nj * 16, kb + b_bs);
                    ldsm4(bh[nj], sb + OF_BH + off);
                    ldsm4(bl[nj], sb + OF_BL + off);
                }
                #pragma unroll
                for (int mi = 0; mi < 2; mi++)
                    #pragma unroll
                    for (int n8 = 0; n8 < 4; n8++) {
                        const unsigned* BH = bh[n8 >> 1] + (n8 & 1) * 2;
                        const unsigned* BL = bl[n8 >> 1] + (n8 & 1) * 2;
                        mma16816(d[mi][n8], ah[mi], BH);
                        mma16816(d[mi][n8], ah[mi], BL);
                        mma16816(d[mi][n8], al[mi], BH);
                    }
            }
            const int rloc = wm * 32 + (lane >> 2);
            const int cbas = c * 128 + wn * 32 + (lane & 3) * 2;
            // K-hi warps store raw partials
            if (ksel == 1) {
                #pragma unroll
                for (int mi = 0; mi < 2; mi++)
                    #pragma unroll
                    for (int n8 = 0; n8 < 4; n8++) {
                        int row = rloc + mi * 16, col = cbas + n8 * 8;
                        *(float2*)(qkv + row * QS + col) =
                            make_float2(d[mi][n8][0], d[mi][n8][1]);
                        *(float2*)(qkv + (row + 8) * QS + col) =
                            make_float2(d[mi][n8][2], d[mi][n8][3]);
                    }
            }
            __syncthreads();   // B consumed; partials visible

            // issue next fill (lookahead): c+1, or h1c0, or proj weights
            {
                const unsigned char* srcH;
                const unsigned char* srcL;
                if (c < 2) { srcH = g_b1h + (c + 1) * 32768; srcL = g_b1l + (c + 1) * 32768; }
                else if (half == 0) { srcH = g_b1h; srcL = g_b1l; }
                else { srcH = g_b2h; srcL = g_b2l; }
                #pragma unroll
                for (int it = 0; it < 4; it++) {
                    int i = tid + it * NT;
                    cp16(sb + OF_BH + i * 16, srcH + i * 16);
                    cp16(sb + OF_BL + i * 16, srcL + i * 16);
                }
                asm volatile("cp.async.commit_group;" ::: "memory");
            }

            // K-lo warps reduce into qkv
            if (ksel == 0) {
                #pragma unroll
                for (int mi = 0; mi < 2; mi++)
                    #pragma unroll
                    for (int n8 = 0; n8 < 4; n8++) {
                        int row = rloc + mi * 16, col = cbas + n8 * 8;
                        float2 p0 = *(float2*)(qkv + row * QS + col);
                        float2 p1 = *(float2*)(qkv + (row + 8) * QS + col);
                        *(float2*)(qkv + row * QS + col) =
                            make_float2(p0.x + d[mi][n8][0], p0.y + d[mi][n8][1]);
                        *(float2*)(qkv + (row + 8) * QS + col) =
                            make_float2(p1.x + d[mi][n8][2], p1.y + d[mi][n8][3]);
                    }
            }
            if (c < 2) {
                asm volatile("cp.async.wait_group 0;" ::: "memory");
                __syncthreads();   // next B ready, qkv adds visible
            }
        }
        __syncthreads();   // qkv complete for this half (fill still in flight)

        // ---- softmax: 512 units (t,h), 1 per thread; no max-subtraction ----
        {
            const float sc2 = 0.0883883476483184405f * 1.4426950408889634f; // scale*log2e
            const int t = (wid << 2) + (lane & 3);
            const int h = lane >> 2;
            const float* row = qkv + t * QS + h * 16;
            float k[16], v[16];
            #pragma unroll
            for (int j4 = 0; j4 < 4; j4++) {
                float4 b = *(const float4*)(row + 128 + j4 * 4);
                float4 cc = *(const float4*)(row + 256 + j4 * 4);
                const float* g1 = sBq + 128 + h * 16 + j4 * 4;
                const float* g2 = g1 + 128;
                k[j4 * 4 + 0] = b.x + g1[0];   k[j4 * 4 + 1] = b.y + g1[1];
                k[j4 * 4 + 2] = b.z + g1[2];   k[j4 * 4 + 3] = b.w + g1[3];
                v[j4 * 4 + 0] = cc.x + g2[0];  v[j4 * 4 + 1] = cc.y + g2[1];
                v[j4 * 4 + 2] = cc.z + g2[2];  v[j4 * 4 + 3] = cc.w + g2[3];
            }
            const float* qb = sBq + h * 16;
            unsigned hi[8], lo[8];
            float oprev = 0.f;
            #pragma unroll 2
            for (int i = 0; i < 16; i++) {
                float ci = (row[i] + qb[i]) * sc2;
                float s = 0.f, acc = 0.f;
                #pragma unroll
                for (int j = 0; j < 16; j++) {
                    float e = ex2f(ci * k[j]);
                    s += e;
                    acc = fmaf(e, v[j], acc);
                }
                float oi = acc * rcpf(s);
                if (i & 1) {
                    float h0 = bfr(oprev), h1 = bfr(oi);
                    hi[i >> 1] = pk2(h0, h1);
                    lo[i >> 1] = pk2(oprev - h0, oi - h1);
                }
                oprev = oi;
            }
            const int m = half * 64 + t;
            unsigned o0 = SWZ(m, h * 32), o1 = SWZ(m, h * 32 + 16);
            *(uint4*)(smem + OF_AH + o0) = make_uint4(hi[0], hi[1], hi[2], hi[3]);
            *(uint4*)(smem + OF_AH + o1) = make_uint4(hi[4], hi[5], hi[6], hi[7]);
            *(uint4*)(smem + OF_AL + o0) = make_uint4(lo[0], lo[1], lo[2], lo[3]);
            *(uint4*)(smem + OF_AL + o1) = make_uint4(lo[4], lo[5], lo[6], lo[7]);
        }
        if (half == 0) {
            asm volatile("cp.async.wait_group 0;" ::: "memory");
            __syncthreads();   // B(h1,c0) ready
        }
    }

    // ---- GEMM2: out[128][128] = A2 @ Wproj + bias (16 warps, 4M x 4N) ----
    asm volatile("cp.async.wait_group 0;" ::: "memory");
    __syncthreads();   // B2 + A2(h1) visible

    const int wm2 = wid >> 2, wn2 = wid & 3;
    float d2[2][4][4] = {};
    const int arow0 = wm2 * 32 + a_r;
    const int brow0 = wn2 * 32 + b_r;
    #pragma unroll
    for (int kc = 0; kc < 8; kc++) {
        const int kb = kc * 32;
        unsigned ah[2][4], al[2][4], bh[2][4], bl[2][4];
        #pragma unroll
        for (int mi = 0; mi < 2; mi++) {
            unsigned off = SWZ(arow0 + mi * 16, kb + a_bs);
            ldsm4(ah[mi], sb + OF_AH + off);
            ldsm4(al[mi], sb + OF_AL + off);
        }
        #pragma unroll
        for (int nj = 0; nj < 2; nj++) {
            unsigned off = SWZ(brow0 + nj * 16, kb + b_bs);
            ldsm4(bh[nj], sb + OF_BH + off);
            ldsm4(bl[nj], sb + OF_BL + off);
        }
        #pragma unroll
        for (int mi = 0; mi < 2; mi++)
            #pragma unroll
            for (int n8 = 0; n8 < 4; n8++) {
                const unsigned* BH = bh[n8 >> 1] + (n8 & 1) * 2;
                const unsigned* BL = bl[n8 >> 1] + (n8 & 1) * 2;
                mma16816(d2[mi][n8], ah[mi], BH);
                mma16816(d2[mi][n8], ah[mi], BL);
                mma16816(d2[mi][n8], al[mi], BH);
            }
    }
    // epilogue: +bias, direct global stores
    {
        float* og = out + tb * 128;
        const int rl = wm2 * 32 + (lane >> 2);
        const int cb = wn2 * 32 + (lane & 3) * 2;
        #pragma unroll
        for (int n8 = 0; n8 < 4; n8++) {
            int col = cb + n8 * 8;
            float b0 = sBp[col], b1 = sBp[col + 1];
            #pragma unroll
            for (int mi = 0; mi < 2; mi++) {
                int r0 = rl + mi * 16;
                *(float2*)(og + r0 * 128 + col) =
                    make_float2(d2[mi][n8][0] + b0, d2[mi][n8][1] + b1);
                *(float2*)(og + (r0 + 8) * 128 + col) =
                    make_float2(d2[mi][n8][2] + b0, d2[mi][n8][3] + b1);
            }
        }
    }
}

extern "C" void kernel_launch(void* const* d_in, const int* in_sizes, int n_in,
                              void* d_out, int out_size)
{
    const float *x = nullptr, *wq = nullptr, *bq = nullptr, *wp = nullptr, *bp = nullptr;
    long long xsz = 0;
    for (int i = 0; i < n_in; i++) {
        switch (in_sizes[i]) {
            case 49152: wq = (const float*)d_in[i]; break;
            case 384:   bq = (const float*)d_in[i]; break;
            case 16384: wp = (const float*)d_in[i]; break;
            case 128:   bp = (const float*)d_in[i]; break;
            default:    x  = (const float*)d_in[i]; xsz = in_sizes[i]; break;
        }
    }
    const int tokens = (int)(xsz / 128);

    prep_weights<<<32, 256>>>(wq, wp);

    cudaFuncSetAttribute(chan_attn_mma,
                         cudaFuncAttributeMaxDynamicSharedMemorySize, SMEM_TOTAL);
    chan_attn_mma<<<tokens / TOK, NT, SMEM_TOTAL>>>(x, bq, bp, (float*)d_out);
}

// round 5
// speedup vs baseline: 1.8154x; 1.0016x over previous
#include <cuda_runtime.h>
#include <cuda_bf16.h>

#define NT 512
#define TOK 128

// Pre-swizzled [N][K] bf16 weight images (hi/lo split). Row = N (out col),
// 128 K values * 2B = 256B per row, 16B-chunk XOR swizzle within row.
__device__ __align__(16) unsigned char g_b1h[98304];   // w_qkv hi  [384][128]
__device__ __align__(16) unsigned char g_b1l[98304];   // w_qkv lo
__device__ __align__(16) unsigned char g_b2h[32768];   // w_proj hi [128][128]
__device__ __align__(16) unsigned char g_b2l[32768];   // w_proj lo

#define SWZ(r, b) ((unsigned)((r) * 256 + ((b) ^ (((r) & 7) << 4))))

// smem map (bytes): biases | A hi | A lo | B hi | B lo | qkv fp32 (64 x 388)
#define OF_BQ   0u
#define OF_BP   1536u
#define OF_AH   2048u
#define OF_AL   34816u
#define OF_BH   67584u
#define OF_BL   100352u
#define OF_QKV  133120u
#define SMEM_TOTAL 232448   // max opt-in
#define QS 388              // qkv row stride in floats

__device__ __forceinline__ unsigned smem_u32(const void* p) {
    unsigned a;
    asm("{ .reg .u64 t; cvta.to.shared.u64 t, %1; cvt.u32.u64 %0, t; }" : "=r"(a) : "l"(p));
    return a;
}
__device__ __forceinline__ unsigned pk2(float a, float b) {
    __nv_bfloat162 t = __floats2bfloat162_rn(a, b);
    return *reinterpret_cast<unsigned*>(&t);
}
__device__ __forceinline__ float bfr(float v) {
    return __bfloat162float(__float2bfloat16_rn(v));
}
__device__ __forceinline__ void ldsm4(unsigned* r, unsigned addr) {
    asm volatile("ldmatrix.sync.aligned.m8n8.x4.shared.b16 {%0,%1,%2,%3}, [%4];"
                 : "=r"(r[0]), "=r"(r[1]), "=r"(r[2]), "=r"(r[3]) : "r"(addr));
}
__device__ __forceinline__ void mma16816(float* d, const unsigned* a, const unsigned* b) {
    asm volatile(
        "mma.sync.aligned.m16n8k16.row.col.f32.bf16.bf16.f32 "
        "{%0,%1,%2,%3}, {%4,%5,%6,%7}, {%8,%9}, {%0,%1,%2,%3};"
        : "+f"(d[0]), "+f"(d[1]), "+f"(d[2]), "+f"(d[3])
        : "r"(a[0]), "r"(a[1]), "r"(a[2]), "r"(a[3]), "r"(b[0]), "r"(b[1]));
}
__device__ __forceinline__ void cp16(unsigned dst, const void* src) {
    asm volatile("cp.async.cg.shared.global [%0], [%1], 16;" :: "r"(dst), "l"(src));
}
__device__ __forceinline__ float ex2f(float x) {
    float r;
    asm("ex2.approx.f32 %0, %1;" : "=f"(r) : "f"(x));
    return r;
}
__device__ __forceinline__ float rcpf(float x) {
    float r;
    asm("rcp.approx.f32 %0, %1;" : "=f"(r) : "f"(x));
    return r;
}

// ---------------- prep: fp32 weights -> swizzled [N][K] bf16 hi/lo images ----------------
__global__ void prep_weights(const float* __restrict__ wq, const float* __restrict__ wp) {
    int i = blockIdx.x * blockDim.x + threadIdx.x;
    if (i < 6144) {                       // w_qkv: 384 n-rows x 16 chunks of 8 k
        int n = i >> 4, kc = i & 15, k0 = kc * 8;
        float hf[8], lf[8];
        #pragma unroll
        for (int j = 0; j < 8; j++) {
            float v = wq[(k0 + j) * 384 + n];
            hf[j] = bfr(v);
            lf[j] = v - hf[j];
        }
        unsigned off = SWZ(n, kc * 16);
        *(uint4*)(g_b1h + off) = make_uint4(pk2(hf[0], hf[1]), pk2(hf[2], hf[3]),
                                            pk2(hf[4], hf[5]), pk2(hf[6], hf[7]));
        *(uint4*)(g_b1l + off) = make_uint4(pk2(lf[0], lf[1]), pk2(lf[2], lf[3]),
                                            pk2(lf[4], lf[5]), pk2(lf[6], lf[7]));
    } else if (i < 8192) {                // w_proj: 128 n-rows x 16 chunks
        int j2 = i - 6144;
        int n = j2 >> 4, kc = j2 & 15, k0 = kc * 8;
        float hf[8], lf[8];
        #pragma unroll
        for (int j = 0; j < 8; j++) {
            float v = wp[(k0 + j) * 128 + n];
            hf[j] = bfr(v);
            lf[j] = v - hf[j];
        }
        unsigned off = SWZ(n, kc * 16);
        *(uint4*)(g_b2h + off) = make_uint4(pk2(hf[0], hf[1]), pk2(hf[2], hf[3]),
                                            pk2(hf[4], hf[5]), pk2(hf[6], hf[7]));
        *(uint4*)(g_b2l + off) = make_uint4(pk2(lf[0], lf[1]), pk2(lf[2], lf[3]),
                                            pk2(lf[4], lf[5]), pk2(lf[6], lf[7]));
    }
}

// ---------------- main fused kernel (512 threads) ----------------
__global__ void __launch_bounds__(NT, 1)
chan_attn_mma(const float* __restrict__ x, const float* __restrict__ bq,
              const float* __restrict__ bp, float* __restrict__ out)
{
    extern __shared__ __align__(16) unsigned char smem[];
    const unsigned sb = smem_u32(smem);
    const int tid = threadIdx.x, wid = tid >> 5, lane = tid & 31;
    const long long tb = (long long)blockIdx.x * TOK;

    float* sBq = (float*)(smem + OF_BQ);
    float* sBp = (float*)(smem + OF_BP);
    float* qkv = (float*)(smem + OF_QKV);

    if (tid < 384) sBq[tid] = bq[tid];
    if (tid < 128) sBp[tid] = bp[tid];

    // prefetch B chunk (h0,c0) via cp.async
    {
        #pragma unroll
        for (int it = 0; it < 4; it++) {
            int i = tid + it * NT;
            cp16(sb + OF_BH + i * 16, g_b1h + i * 16);
            cp16(sb + OF_BL + i * 16, g_b1l + i * 16);
        }
        asm volatile("cp.async.commit_group;" ::: "memory");
    }

    // build A image from x (hi/lo bf16, swizzled [m][k]) — overlaps cp.async
    {
        const float4* x4 = (const float4*)(x + tb * 128);
        #pragma unroll
        for (int it = 0; it < 8; it++) {
            int i = tid + it * NT;
            int m = i >> 5, c4 = i & 31;
            float4 v = x4[i];
            float h0 = bfr(v.x), h1 = bfr(v.y), h2 = bfr(v.z), h3 = bfr(v.w);
            unsigned off = SWZ(m, c4 * 8);
            *(uint2*)(smem + OF_AH + off) = make_uint2(pk2(h0, h1), pk2(h2, h3));
            *(uint2*)(smem + OF_AL + off) =
                make_uint2(pk2(v.x - h0, v.y - h1), pk2(v.z - h2, v.w - h3));
        }
    }
    asm volatile("cp.async.wait_group 0;" ::: "memory");
    __syncthreads();

    // ldmatrix lane address components
    const int a_r = (lane & 7) + ((lane >> 3) & 1) * 8;
    const int a_bs = (lane >> 4) * 16;
    const int b_r = (lane & 7) + (lane >> 4) * 8;
    const int b_bs = ((lane >> 3) & 1) * 16;

    const int w8 = wid & 7;          // tile id for GEMM1 (K-split pairs)
    const int ksel = wid >> 3;       // 0: kc 0-3, 1: kc 4-7
    const int wm = w8 >> 2, wn = w8 & 3;     // 2M x 4N over (64 x 128)

    #pragma unroll 1
    for (int half = 0; half < 2; half++) {
        #pragma unroll 1
        for (int c = 0; c < 3; c++) {
            // B for (half, c) is resident & visible here
            float d[2][4][4] = {};
            const int arow0 = half * 64 + wm * 32 + a_r;
            const int brow0 = wn * 32 + b_r;
            #pragma unroll
            for (int j = 0; j < 4; j++) {
                const int kb = (ksel * 4 + j) * 32;
                unsigned ah[2][4], al[2][4], bh[2][4], bl[2][4];
                #pragma unroll
                for (int mi = 0; mi < 2; mi++) {
                    unsigned off = SWZ(arow0 + mi * 16, kb + a_bs);
                    ldsm4(ah[mi], sb + OF_AH + off);
                    ldsm4(al[mi], sb + OF_AL + off);
                }
                #pragma unroll
                for (int nj = 0; nj < 2; nj++) {
                    unsigned off = SWZ(brow0 + nj * 16, kb + b_bs);
                    ldsm4(bh[nj], sb + OF_BH + off);
                    ldsm4(bl[nj], sb + OF_BL + off);
                }
                #pragma unroll
                for (int mi = 0; mi < 2; mi++)
                    #pragma unroll
                    for (int n8 = 0; n8 < 4; n8++) {
                        const unsigned* BH = bh[n8 >> 1] + (n8 & 1) * 2;
                        const unsigned* BL = bl[n8 >> 1] + (n8 & 1) * 2;
                        mma16816(d[mi][n8], ah[mi], BH);
                        mma16816(d[mi][n8], ah[mi], BL);
                        mma16816(d[mi][n8], al[mi], BH);
                    }
            }
            const int rloc = wm * 32 + (lane >> 2);
            const int cbas = c * 128 + wn * 32 + (lane & 3) * 2;
            // K-hi warps store raw partials
            if (ksel == 1) {
                #pragma unroll
                for (int mi = 0; mi < 2; mi++)
                    #pragma unroll
                    for (int n8 = 0; n8 < 4; n8++) {
                        int row = rloc + mi * 16, col = cbas + n8 * 8;
                        *(float2*)(qkv + row * QS + col) =
                            make_float2(d[mi][n8][0], d[mi][n8][1]);
                        *(float2*)(qkv + (row + 8) * QS + col) =
                            make_float2(d[mi][n8][2], d[mi][n8][3]);
                    }
            }
            __syncthreads();   // B consumed; partials visible

            // issue next fill (lookahead): c+1, or h1c0, or proj weights
            {
                const unsigned char* srcH;
                const unsigned char* srcL;
                if (c < 2) { srcH = g_b1h + (c + 1) * 32768; srcL = g_b1l + (c + 1) * 32768; }
                else if (half == 0) { srcH = g_b1h; srcL = g_b1l; }
                else { srcH = g_b2h; srcL = g_b2l; }
                #pragma unroll
                for (int it = 0; it < 4; it++) {
                    int i = tid + it * NT;
                    cp16(sb + OF_BH + i * 16, srcH + i * 16);
                    cp16(sb + OF_BL + i * 16, srcL + i * 16);
                }
                asm volatile("cp.async.commit_group;" ::: "memory");
            }

            // K-lo warps reduce into qkv
            if (ksel == 0) {
                #pragma unroll
                for (int mi = 0; mi < 2; mi++)
                    #pragma unroll
                    for (int n8 = 0; n8 < 4; n8++) {
                        int row = rloc + mi * 16, col = cbas + n8 * 8;
                        float2 p0 = *(float2*)(qkv + row * QS + col);
                        float2 p1 = *(float2*)(qkv + (row + 8) * QS + col);
                        *(float2*)(qkv + row * QS + col) =
                            make_float2(p0.x + d[mi][n8][0], p0.y + d[mi][n8][1]);
                        *(float2*)(qkv + (row + 8) * QS + col) =
                            make_float2(p1.x + d[mi][n8][2], p1.y + d[mi][n8][3]);
                    }
            }
            if (c < 2) {
                asm volatile("cp.async.wait_group 0;" ::: "memory");
                __syncthreads();   // next B ready, qkv adds visible
            }
        }
        __syncthreads();   // qkv complete for this half (fill still in flight)

        // ---- softmax: 512 units (t,h), 1 per thread; no max-subtraction ----
        {
            const float sc2 = 0.0883883476483184405f * 1.4426950408889634f; // scale*log2e
            const int t = (wid << 2) + (lane & 3);
            const int h = lane >> 2;
            const float* row = qkv + t * QS + h * 16;
            float k[16], v[16];
            #pragma unroll
            for (int j4 = 0; j4 < 4; j4++) {
                float4 b = *(const float4*)(row + 128 + j4 * 4);
                float4 cc = *(const float4*)(row + 256 + j4 * 4);
                const float* g1 = sBq + 128 + h * 16 + j4 * 4;
                const float* g2 = g1 + 128;
                k[j4 * 4 + 0] = b.x + g1[0];   k[j4 * 4 + 1] = b.y + g1[1];
                k[j4 * 4 + 2] = b.z + g1[2];   k[j4 * 4 + 3] = b.w + g1[3];
                v[j4 * 4 + 0] = cc.x + g2[0];  v[j4 * 4 + 1] = cc.y + g2[1];
                v[j4 * 4 + 2] = cc.z + g2[2];  v[j4 * 4 + 3] = cc.w + g2[3];
            }
            const float* qb = sBq + h * 16;
            unsigned hi[8], lo[8];
            float oprev = 0.f;
            #pragma unroll 2
            for (int i = 0; i < 16; i++) {
                float ci = (row[i] + qb[i]) * sc2;
                float s = 0.f, acc = 0.f;
                #pragma unroll
                for (int j = 0; j < 16; j++) {
                    float e = ex2f(ci * k[j]);
                    s += e;
                    acc = fmaf(e, v[j], acc);
                }
                float oi = acc * rcpf(s);
                if (i & 1) {
                    float h0 = bfr(oprev), h1 = bfr(oi);
                    hi[i >> 1] = pk2(h0, h1);
                    lo[i >> 1] = pk2(oprev - h0, oi - h1);
                }
                oprev = oi;
            }
            const int m = half * 64 + t;
            unsigned o0 = SWZ(m, h * 32), o1 = SWZ(m, h * 32 + 16);
            *(uint4*)(smem + OF_AH + o0) = make_uint4(hi[0], hi[1], hi[2], hi[3]);
            *(uint4*)(smem + OF_AH + o1) = make_uint4(hi[4], hi[5], hi[6], hi[7]);
            *(uint4*)(smem + OF_AL + o0) = make_uint4(lo[0], lo[1], lo[2], lo[3]);
            *(uint4*)(smem + OF_AL + o1) = make_uint4(lo[4], lo[5], lo[6], lo[7]);
        }
        if (half == 0) {
            asm volatile("cp.async.wait_group 0;" ::: "memory");
            __syncthreads();   // B(h1,c0) ready
        }
    }

    // ---- GEMM2: out[128][128] = A2 @ Wproj + bias (16 warps, 4M x 4N) ----
    asm volatile("cp.async.wait_group 0;" ::: "memory");
    __syncthreads();   // B2 + A2(h1) visible

    const int wm2 = wid >> 2, wn2 = wid & 3;
    float d2[2][4][4] = {};
    const int arow0 = wm2 * 32 + a_r;
    const int brow0 = wn2 * 32 + b_r;
    #pragma unroll
    for (int kc = 0; kc < 8; kc++) {
        const int kb = kc * 32;
        unsigned ah[2][4], al[2][4], bh[2][4], bl[2][4];
        #pragma unroll
        for (int mi = 0; mi < 2; mi++) {
            unsigned off = SWZ(arow0 + mi * 16, kb + a_bs);
            ldsm4(ah[mi], sb + OF_AH + off);
            ldsm4(al[mi], sb + OF_AL + off);
        }
        #pragma unroll
        for (int nj = 0; nj < 2; nj++) {
            unsigned off = SWZ(brow0 + nj * 16, kb + b_bs);
            ldsm4(bh[nj], sb + OF_BH + off);
            ldsm4(bl[nj], sb + OF_BL + off);
        }
        #pragma unroll
        for (int mi = 0; mi < 2; mi++)
            #pragma unroll
            for (int n8 = 0; n8 < 4; n8++) {
                const unsigned* BH = bh[n8 >> 1] + (n8 & 1) * 2;
                const unsigned* BL = bl[n8 >> 1] + (n8 & 1) * 2;
                mma16816(d2[mi][n8], ah[mi], BH);
                mma16816(d2[mi][n8], ah[mi], BL);
                mma16816(d2[mi][n8], al[mi], BH);
            }
    }
    // epilogue: +bias, direct global stores
    {
        float* og = out + tb * 128;
        const int rl = wm2 * 32 + (lane >> 2);
        const int cb = wn2 * 32 + (lane & 3) * 2;
        #pragma unroll
        for (int n8 = 0; n8 < 4; n8++) {
            int col = cb + n8 * 8;
            float b0 = sBp[col], b1 = sBp[col + 1];
            #pragma unroll
            for (int mi = 0; mi < 2; mi++) {
                int r0 = rl + mi * 16;
                *(float2*)(og + r0 * 128 + col) =
                    make_float2(d2[mi][n8][0] + b0, d2[mi][n8][1] + b1);
                *(float2*)(og + (r0 + 8) * 128 + col) =
                    make_float2(d2[mi][n8][2] + b0, d2[mi][n8][3] + b1);
            }
        }
    }
}

extern "C" void kernel_launch(void* const* d_in, const int* in_sizes, int n_in,
                              void* d_out, int out_size)
{
    const float *x = nullptr, *wq = nullptr, *bq = nullptr, *wp = nullptr, *bp = nullptr;
    long long xsz = 0;
    for (int i = 0; i < n_in; i++) {
        switch (in_sizes[i]) {
            case 49152: wq = (const float*)d_in[i]; break;
            case 384:   bq = (const float*)d_in[i]; break;
            case 16384: wp = (const float*)d_in[i]; break;
            case 128:   bp = (const float*)d_in[i]; break;
            default:    x  = (const float*)d_in[i]; xsz = in_sizes[i]; break;
        }
    }
    const int tokens = (int)(xsz / 128);

    prep_weights<<<32, 256>>>(wq, wp);

    cudaFuncSetAttribute(chan_attn_mma,
                         cudaFuncAttributeMaxDynamicSharedMemorySize, SMEM_TOTAL);
    chan_attn_mma<<<tokens / TOK, NT, SMEM_TOTAL>>>(x, bq, bp, (float*)d_out);
}

// round 7
// speedup vs baseline: 2.1293x; 1.1729x over previous
#include <cuda_runtime.h>
#include <cuda_bf16.h>

#define NT 256
#define TOK 128

// Pre-swizzled [N][K] bf16 weight images (hi/lo split), 256B rows, XOR-16B swizzle.
// g_b1: w_qkv with HEAD-GROUPED column order: image row n' = h*48 + blk*16 + i
//       (blk 0=q,1=k,2=v) maps to original col blk*128 + h*16 + i.
__device__ __align__(16) unsigned char g_b1h[98304];
__device__ __align__(16) unsigned char g_b1l[98304];
__device__ __align__(16) unsigned char g_b2h[32768];   // w_proj [n][k]
__device__ __align__(16) unsigned char g_b2l[32768];

#define SWZ(r, b) ((unsigned)((r) * 256 + ((b) ^ (((r) & 7) << 4))))

// smem map (bytes)
#define OF_BQ   0u        // 1536
#define OF_BP   1536u     // 512
#define OF_SCR  2048u     // 16384: A2-frag exchange [wid][slot16][lane]
#define OF_AH   18432u    // 32768: x image hi
#define OF_AL   51200u    // 32768: x image lo
#define OF_B2H  83968u    // 32768
#define OF_B2L  116736u   // 32768
#define OF_B1H  149504u   // 24576: current round (2 heads, 96 rows)
#define OF_B1L  174080u   // 24576
#define SMEM_TOTAL 198656

__device__ __forceinline__ unsigned smem_u32(const void* p) {
    unsigned a;
    asm("{ .reg .u64 t; cvta.to.shared.u64 t, %1; cvt.u32.u64 %0, t; }" : "=r"(a) : "l"(p));
    return a;
}
__device__ __forceinline__ unsigned pk2(float a, float b) {
    __nv_bfloat162 t = __floats2bfloat162_rn(a, b);
    return *reinterpret_cast<unsigned*>(&t);
}
__device__ __forceinline__ float bfr(float v) {
    return __bfloat162float(__float2bfloat16_rn(v));
}
__device__ __forceinline__ void ldsm4(unsigned* r, unsigned addr) {
    asm volatile("ldmatrix.sync.aligned.m8n8.x4.shared.b16 {%0,%1,%2,%3}, [%4];"
                 : "=r"(r[0]), "=r"(r[1]), "=r"(r[2]), "=r"(r[3]) : "r"(addr));
}
__device__ __forceinline__ void mma16816(float* d, const unsigned* a, const unsigned* b) {
    asm volatile(
        "mma.sync.aligned.m16n8k16.row.col.f32.bf16.bf16.f32 "
        "{%0,%1,%2,%3}, {%4,%5,%6,%7}, {%8,%9}, {%0,%1,%2,%3};"
        : "+f"(d[0]), "+f"(d[1]), "+f"(d[2]), "+f"(d[3])
        : "r"(a[0]), "r"(a[1]), "r"(a[2]), "r"(a[3]), "r"(b[0]), "r"(b[1]));
}
__device__ __forceinline__ void cp16(unsigned dst, const void* src) {
    asm volatile("cp.async.cg.shared.global [%0], [%1], 16;" :: "r"(dst), "l"(src));
}
__device__ __forceinline__ float ex2f(float x) {
    float r; asm("ex2.approx.f32 %0, %1;" : "=f"(r) : "f"(x)); return r;
}
__device__ __forceinline__ float rcpf(float x) {
    float r; asm("rcp.approx.f32 %0, %1;" : "=f"(r) : "f"(x)); return r;
}

// ---------------- prep: fp32 weights -> swizzled bf16 hi/lo images ----------------
__global__ void prep_weights(const float* __restrict__ wq, const float* __restrict__ wp) {
    int i = blockIdx.x * blockDim.x + threadIdx.x;
    if (i < 6144) {                        // w_qkv: 384 head-grouped rows x 16 k-chunks
        int n = i >> 4, kc = i & 15, k0 = kc * 8;
        int h = n / 48, rem = n % 48, blk = rem >> 4, ii = rem & 15;
        int col = blk * 128 + h * 16 + ii; // original w_qkv column
        float hf[8], lf[8];
        #pragma unroll
        for (int j = 0; j < 8; j++) {
            float v = wq[(k0 + j) * 384 + col];
            hf[j] = bfr(v);
            lf[j] = v - hf[j];
        }
        unsigned off = SWZ(n, kc * 16);
        *(uint4*)(g_b1h + off) = make_uint4(pk2(hf[0], hf[1]), pk2(hf[2], hf[3]),
                                            pk2(hf[4], hf[5]), pk2(hf[6], hf[7]));
        *(uint4*)(g_b1l + off) = make_uint4(pk2(lf[0], lf[1]), pk2(lf[2], lf[3]),
                                            pk2(lf[4], lf[5]), pk2(lf[6], lf[7]));
    } else if (i < 8192) {                 // w_proj: 128 rows x 16 chunks
        int j2 = i - 6144;
        int n = j2 >> 4, kc = j2 & 15, k0 = kc * 8;
        float hf[8], lf[8];
        #pragma unroll
        for (int j = 0; j < 8; j++) {
            float v = wp[(k0 + j) * 128 + n];
            hf[j] = bfr(v);
            lf[j] = v - hf[j];
        }
        unsigned off = SWZ(n, kc * 16);
        *(uint4*)(g_b2h + off) = make_uint4(pk2(hf[0], hf[1]), pk2(hf[2], hf[3]),
                                            pk2(hf[4], hf[5]), pk2(hf[6], hf[7]));
        *(uint4*)(g_b2l + off) = make_uint4(pk2(lf[0], lf[1]), pk2(lf[2], lf[3]),
                                            pk2(lf[4], lf[5]), pk2(lf[6], lf[7]));
    }
}

// ---------------- main fused kernel: register-resident softmax ----------------
__global__ void __launch_bounds__(NT, 1)
chan_attn_reg(const float* __restrict__ x, const float* __restrict__ bq,
              const float* __restrict__ bp, float* __restrict__ out)
{
    extern __shared__ __align__(16) unsigned char smem[];
    const unsigned sb = smem_u32(smem);
    const int tid = threadIdx.x, wid = tid >> 5, lane = tid & 31;
    const int wm = wid >> 1, wh = wid & 1, p = lane & 3;
    const long long tb = (long long)blockIdx.x * TOK;

    float* sBq = (float*)(smem + OF_BQ);
    float* sBp = (float*)(smem + OF_BP);
    // FIX (round 6 bug): full coverage of all 384 bias elements at NT=256
    for (int i = tid; i < 384; i += NT) sBq[i] = bq[i];
    if (tid < 128) sBp[tid] = bp[tid];

    // prologue cp.async: B2 (64KB) + B1 round0 (48KB)
    #pragma unroll
    for (int it = 0; it < 8; it++) {
        int i = tid + it * NT;
        cp16(sb + OF_B2H + i * 16, g_b2h + i * 16);
        cp16(sb + OF_B2L + i * 16, g_b2l + i * 16);
    }
    #pragma unroll
    for (int it = 0; it < 6; it++) {
        int i = tid + it * NT;
        cp16(sb + OF_B1H + i * 16, g_b1h + i * 16);
        cp16(sb + OF_B1L + i * 16, g_b1l + i * 16);
    }
    asm volatile("cp.async.commit_group;" ::: "memory");

    // build A image from x (hi/lo bf16, swizzled [m][k]) — overlaps cp.async drain
    {
        const float4* x4 = (const float4*)(x + tb * 128);
        #pragma unroll
        for (int it = 0; it < 16; it++) {
            int i = tid + it * NT;
            int m = i >> 5, c4 = i & 31;
            float4 v = x4[i];
            float h0 = bfr(v.x), h1 = bfr(v.y), h2 = bfr(v.z), h3 = bfr(v.w);
            unsigned off = SWZ(m, c4 * 8);
            *(uint2*)(smem + OF_AH + off) = make_uint2(pk2(h0, h1), pk2(h2, h3));
            *(uint2*)(smem + OF_AL + off) =
                make_uint2(pk2(v.x - h0, v.y - h1), pk2(v.z - h2, v.w - h3));
        }
    }

    const int a_r = (lane & 7) + ((lane >> 3) & 1) * 8;
    const int a_bs = (lane >> 4) * 16;
    const int b_r = (lane & 7) + (lane >> 4) * 8;
    const int b_bs = ((lane >> 3) & 1) * 16;

    float d2[2][8][4] = {};   // GEMM2 accumulator: m32 x n64, lives across rounds

    unsigned* scr = (unsigned*)(smem + OF_SCR);
    const int sbase = wid * 512 + lane;
    const int pbase = (wid ^ 1) * 512 + lane;

    #pragma unroll 1
    for (int r = 0; r < 4; r++) {
        asm volatile("cp.async.wait_group 0;" ::: "memory");
        __syncthreads();   // B1(round r) resident

        // ---- GEMM1: d1 = A1[m32] @ B1[head 2r+wh]  (m32 x n48, K=128) ----
        float d1[2][6][4] = {};
        #pragma unroll
        for (int kc = 0; kc < 8; kc++) {
            const int kb = kc * 32;
            unsigned ah[2][4], al[2][4], bh[3][4], bl[3][4];
            #pragma unroll
            for (int mi = 0; mi < 2; mi++) {
                unsigned off = SWZ(wm * 32 + mi * 16 + a_r, kb + a_bs);
                ldsm4(ah[mi], sb + OF_AH + off);
                ldsm4(al[mi], sb + OF_AL + off);
            }
            #pragma unroll
            for (int g = 0; g < 3; g++) {
                unsigned off = SWZ(wh * 48 + g * 16 + b_r, kb + b_bs);
                ldsm4(bh[g], sb + OF_B1H + off);
                ldsm4(bl[g], sb + OF_B1L + off);
            }
            #pragma unroll
            for (int mi = 0; mi < 2; mi++)
                #pragma unroll
                for (int j = 0; j < 6; j++) {
                    const unsigned* BH = bh[j >> 1] + (j & 1) * 2;
                    const unsigned* BL = bl[j >> 1] + (j & 1) * 2;
                    mma16816(d1[mi][j], ah[mi], BH);
                    mma16816(d1[mi][j], ah[mi], BL);
                    mma16816(d1[mi][j], al[mi], BH);
                }
        }
        __syncthreads();   // all warps done reading B1

        // refill B1 for next round (drains under softmax/GEMM2)
        if (r < 3) {
            const unsigned char* s1 = g_b1h + (r + 1) * 24576;
            const unsigned char* s2 = g_b1l + (r + 1) * 24576;
            #pragma unroll
            for (int it = 0; it < 6; it++) {
                int i = tid + it * NT;
                cp16(sb + OF_B1H + i * 16, s1 + i * 16);
                cp16(sb + OF_B1L + i * 16, s2 + i * 16);
            }
            asm volatile("cp.async.commit_group;" ::: "memory");
        }

        // ---- in-register softmax for head hh; output = GEMM2 A-fragments ----
        const int hh = 2 * r + wh;
        unsigned a2h[2][4], a2l[2][4];
        {
            const float scl2 = 0.0883883476483184405f * 1.4426950408889634f;
            const int c0 = 2 * p, c2 = 8 + 2 * p;
            float qb0 = sBq[hh * 16 + c0], qb1 = sBq[hh * 16 + c0 + 1];
            float qb2 = sBq[hh * 16 + c2], qb3 = sBq[hh * 16 + c2 + 1];
            float kb0 = sBq[128 + hh * 16 + c0], kb1 = sBq[128 + hh * 16 + c0 + 1];
            float kb2 = sBq[128 + hh * 16 + c2], kb3 = sBq[128 + hh * 16 + c2 + 1];
            float vb0 = sBq[256 + hh * 16 + c0], vb1 = sBq[256 + hh * 16 + c0 + 1];
            float vb2 = sBq[256 + hh * 16 + c2], vb3 = sBq[256 + hh * 16 + c2 + 1];

            #pragma unroll
            for (int mi = 0; mi < 2; mi++) {
                float o[2][4];
                #pragma unroll
                for (int rh = 0; rh < 2; rh++) {
                    float kk0 = d1[mi][2][rh * 2 + 0] + kb0;
                    float kk1 = d1[mi][2][rh * 2 + 1] + kb1;
                    float kk2 = d1[mi][3][rh * 2 + 0] + kb2;
                    float kk3 = d1[mi][3][rh * 2 + 1] + kb3;
                    float vv0 = d1[mi][4][rh * 2 + 0] + vb0;
                    float vv1 = d1[mi][4][rh * 2 + 1] + vb1;
                    float vv2 = d1[mi][5][rh * 2 + 0] + vb2;
                    float vv3 = d1[mi][5][rh * 2 + 1] + vb3;
                    float kf[16], vf[16];
                    #pragma unroll
                    for (int pp = 0; pp < 4; pp++) {
                        int sl = (lane & ~3) | pp;
                        kf[2 * pp]         = __shfl_sync(0xffffffffu, kk0, sl);
                        kf[2 * pp + 1]     = __shfl_sync(0xffffffffu, kk1, sl);
                        kf[8 + 2 * pp]     = __shfl_sync(0xffffffffu, kk2, sl);
                        kf[8 + 2 * pp + 1] = __shfl_sync(0xffffffffu, kk3, sl);
                        vf[2 * pp]         = __shfl_sync(0xffffffffu, vv0, sl);
                        vf[2 * pp + 1]     = __shfl_sync(0xffffffffu, vv1, sl);
                        vf[8 + 2 * pp]     = __shfl_sync(0xffffffffu, vv2, sl);
                        vf[8 + 2 * pp + 1] = __shfl_sync(0xffffffffu, vv3, sl);
                    }
                    float qv[4] = {qb0, qb1, qb2, qb3};
                    #pragma unroll
                    for (int i = 0; i < 4; i++) {
                        float ci = (d1[mi][i >> 1][rh * 2 + (i & 1)] + qv[i]) * scl2;
                        float s = 0.f, a = 0.f;
                        #pragma unroll
                        for (int j = 0; j < 16; j++) {
                            float e = ex2f(ci * kf[j]);
                            s += e;
                            a = fmaf(e, vf[j], a);
                        }
                        o[rh][i] = a * rcpf(s);
                    }
                }
                float h00 = bfr(o[0][0]), h01 = bfr(o[0][1]);
                float h10 = bfr(o[1][0]), h11 = bfr(o[1][1]);
                float h02 = bfr(o[0][2]), h03 = bfr(o[0][3]);
                float h12 = bfr(o[1][2]), h13 = bfr(o[1][3]);
                a2h[mi][0] = pk2(h00, h01);  a2h[mi][1] = pk2(h10, h11);
                a2h[mi][2] = pk2(h02, h03);  a2h[mi][3] = pk2(h12, h13);
                a2l[mi][0] = pk2(o[0][0] - h00, o[0][1] - h01);
                a2l[mi][1] = pk2(o[1][0] - h10, o[1][1] - h11);
                a2l[mi][2] = pk2(o[0][2] - h02, o[0][3] - h03);
                a2l[mi][3] = pk2(o[1][2] - h12, o[1][3] - h13);
            }
        }

        // ---- exchange A2 fragments with pair warp (other head of round) ----
        #pragma unroll
        for (int mi = 0; mi < 2; mi++)
            #pragma unroll
            for (int e = 0; e < 4; e++) {
                scr[sbase + (mi * 4 + e) * 32] = a2h[mi][e];
                scr[sbase + (8 + mi * 4 + e) * 32] = a2l[mi][e];
            }
        asm volatile("bar.sync %0, %1;" :: "r"(1 + wm), "r"(64) : "memory");
        unsigned p2h[2][4], p2l[2][4];
        #pragma unroll
        for (int mi = 0; mi < 2; mi++)
            #pragma unroll
            for (int e = 0; e < 4; e++) {
                p2h[mi][e] = scr[pbase + (mi * 4 + e) * 32];
                p2l[mi][e] = scr[pbase + (8 + mi * 4 + e) * 32];
            }

        // ---- GEMM2 incremental accumulation: both heads of this round ----
        #pragma unroll
        for (int which = 0; which < 2; which++) {
            const unsigned (*AH)[4] = which ? p2h : a2h;
            const unsigned (*AL)[4] = which ? p2l : a2l;
            const int hd = 2 * r + (which ? (wh ^ 1) : wh);
            const int kb2 = hd * 32;
            unsigned b2h_[4][4], b2l_[4][4];
            #pragma unroll
            for (int g = 0; g < 4; g++) {
                unsigned off = SWZ(wh * 64 + g * 16 + b_r, kb2 + b_bs);
                ldsm4(b2h_[g], sb + OF_B2H + off);
                ldsm4(b2l_[g], sb + OF_B2L + off);
            }
            #pragma unroll
            for (int mi = 0; mi < 2; mi++)
                #pragma unroll
                for (int j = 0; j < 8; j++) {
                    const unsigned* BH = b2h_[j >> 1] + (j & 1) * 2;
                    const unsigned* BL = b2l_[j >> 1] + (j & 1) * 2;
                    mma16816(d2[mi][j], AH[mi], BH);
                    mma16816(d2[mi][j], AH[mi], BL);
                    mma16816(d2[mi][j], AL[mi], BH);
                }
        }
        __syncthreads();   // scratch reads done before next round reuses it
    }

    // ---- epilogue: d2 + bias -> gmem ----
    {
        float* og = out + tb * 128;
        const int rl = wm * 32 + (lane >> 2);
        const int cb = wh * 64 + p * 2;
        #pragma unroll
        for (int j = 0; j < 8; j++) {
            int col = cb + j * 8;
            float b0 = sBp[col], b1 = sBp[col + 1];
            #pragma unroll
            for (int mi = 0; mi < 2; mi++) {
                int r0 = rl + mi * 16;
                *(float2*)(og + r0 * 128 + col) =
                    make_float2(d2[mi][j][0] + b0, d2[mi][j][1] + b1);
                *(float2*)(og + (r0 + 8) * 128 + col) =
                    make_float2(d2[mi][j][2] + b0, d2[mi][j][3] + b1);
            }
        }
    }
}

extern "C" void kernel_launch(void* const* d_in, const int* in_sizes, int n_in,
                              void* d_out, int out_size)
{
    const float *x = nullptr, *wq = nullptr, *bq = nullptr, *wp = nullptr, *bp = nullptr;
    long long xsz = 0;
    for (int i = 0; i < n_in; i++) {
        switch (in_sizes[i]) {
            case 49152: wq = (const float*)d_in[i]; break;
            case 384:   bq = (const float*)d_in[i]; break;
            case 16384: wp = (const float*)d_in[i]; break;
            case 128:   bp = (const float*)d_in[i]; break;
            default:    x  = (const float*)d_in[i]; xsz = in_sizes[i]; break;
        }
    }
    const int tokens = (int)(xsz / 128);

    prep_weights<<<32, 256>>>(wq, wp);

    cudaFuncSetAttribute(chan_attn_reg,
                         cudaFuncAttributeMaxDynamicSharedMemorySize, SMEM_TOTAL);
    chan_attn_reg<<<tokens / TOK, NT, SMEM_TOTAL>>>(x, bq, bp, (float*)d_out);
}